// round 4
// baseline (speedup 1.0000x reference)
#include <cuda_runtime.h>
#include <math.h>

#define NN 8192
#define NB 256          // value bins over Y in [0, 100)

// ---------------- device scratch (no allocations allowed) ----------------
struct Scratch {                 // this whole struct is memset to 0 each launch
    int    count[NB];            // bin histogram
    int    cursor[NB];           // scatter cursors (delta from bin start)
    double binSumE[NB];          // per-bin sum of exp(theta)
    double acc;                  // loss accumulator
    int    done;                 // last-block-done counter
    int    pad;
};
__device__ Scratch g;
__device__ float4  g_data[NN];    // (Y, e, theta, c) original order
__device__ float4  g_sorted[NN];  // grouped by bin

__device__ __forceinline__ int bin_of(float y) {
    int b = (int)(y * (256.0f / 100.0f));
    return min(NB - 1, max(0, b));
}

// ---------------- kernel 1: elementwise prep + histogram ----------------
__global__ void k_prep(const float* __restrict__ Y,
                       const int*   __restrict__ c,
                       const float* __restrict__ logits) {
    int i = blockIdx.x * blockDim.x + threadIdx.x;
    float y = Y[i];
    float x = logits[i];
    float t = 1.0f / (1.0f + __expf(-x));   // sigmoid
    float e = __expf(t);
    g_data[i] = make_float4(y, e, t, (float)c[i]);
    int b = bin_of(y);
    atomicAdd(&g.count[b], 1);
    atomicAdd(&g.binSumE[b], (double)e);
}

// ---------------- kernel 2: counting-sort scatter ----------------
// Each block (256 threads) redundantly computes the 256-bin exclusive offsets
// via an in-smem scan (cheap), then scatters its 256 elements.
__global__ void k_scatter() {
    __shared__ int sc[NB];    // inclusive prefix of counts
    __shared__ int scnt[NB];  // raw counts
    int t = threadIdx.x;

    int cv = g.count[t];
    scnt[t] = cv;
    sc[t]   = cv;
    __syncthreads();
    #pragma unroll
    for (int o = 1; o < NB; o <<= 1) {
        int v = (t >= o) ? sc[t - o] : 0;
        __syncthreads();
        sc[t] += v;
        __syncthreads();
    }

    int i = blockIdx.x * blockDim.x + t;
    float4 d = g_data[i];
    int b = bin_of(d.x);
    int start = sc[b] - scnt[b];
    int pos = start + atomicAdd(&g.cursor[b], 1);
    g_sorted[pos] = d;
}

// ---------------- kernel 3: risk + loss + finish ----------------
__global__ void k_main(float* __restrict__ out) {
    __shared__ int    sc[NB];     // inclusive prefix of counts
    __shared__ int    scnt[NB];
    __shared__ double ssuf[NB];   // inclusive suffix of bin sums
    __shared__ double sorig[NB];  // raw bin sums
    __shared__ double blk[8];

    int t = threadIdx.x;
    int cv = g.count[t];
    double ev = g.binSumE[t];
    scnt[t] = cv;  sc[t] = cv;
    sorig[t] = ev; ssuf[t] = ev;
    __syncthreads();
    #pragma unroll
    for (int o = 1; o < NB; o <<= 1) {
        int    v  = (t >= o)      ? sc[t - o]   : 0;
        double dv = (t + o < NB)  ? ssuf[t + o] : 0.0;
        __syncthreads();
        sc[t]   += v;
        ssuf[t] += dv;
        __syncthreads();
    }

    int s = blockIdx.x * blockDim.x + t;
    float4 d = g_sorted[s];
    int b = bin_of(d.x);

    // risk = sum over strictly-higher bins (double, no cancellation)
    //      + within-bin compare-sum (exact wrt reference semantics)
    float r = (float)(ssuf[b] - sorig[b]);
    int j0 = sc[b] - scnt[b];
    int j1 = sc[b];
    float y = d.x;
    for (int j = j0; j < j1; j++) {          // ~32 iters, warp-broadcast loads
        float4 dj = g_sorted[j];
        if (dj.x >= y) r += dj.y;
    }

    float contrib = d.w * (d.z - logf(r));   // c * (theta - log risk)

    // block reduce
    #pragma unroll
    for (int o = 16; o; o >>= 1)
        contrib += __shfl_xor_sync(0xffffffffu, contrib, o);
    if ((t & 31) == 0) blk[t >> 5] = (double)contrib;
    __syncthreads();
    if (t < 8) {
        double v = blk[t];
        #pragma unroll
        for (int o = 4; o; o >>= 1)
            v += __shfl_xor_sync(0x000000ffu, v, o);
        if (t == 0) {
            atomicAdd(&g.acc, v);
            __threadfence();
            int prev = atomicAdd(&g.done, 1);
            if (prev == (int)gridDim.x - 1) {
                double a = atomicAdd(&g.acc, 0.0);   // atomic read
                out[0] = (float)(-a / (double)NN);
            }
        }
    }
}

// ---------------- launch ----------------
extern "C" void kernel_launch(void* const* d_in, const int* in_sizes, int n_in,
                              void* d_out, int out_size) {
    const float* Y      = (const float*)d_in[0];
    const int*   c      = (const int*)  d_in[1];
    const float* logits = (const float*)d_in[2];
    float* out = (float*)d_out;
    (void)in_sizes; (void)n_in; (void)out_size;

    void* gptr = nullptr;
    cudaGetSymbolAddress(&gptr, g);
    cudaMemsetAsync(gptr, 0, sizeof(Scratch));   // graph memset node

    k_prep   <<<NN / 256, 256>>>(Y, c, logits);
    k_scatter<<<NN / 256, 256>>>();
    k_main   <<<NN / 256, 256>>>(out);
}